// round 6
// baseline (speedup 1.0000x reference)
#include <cuda_runtime.h>
#include <cuda_bf16.h>
#include <cstdint>

// Problem constants (fixed by the dataset)
#define B_DIM 32
#define L_DIM 256
#define H_DIM 512
#define H4    (H_DIM / 4)      // 128 float4 per row
#define ZFPB  16               // tail frames per zero-fill block

// ---------------------------------------------------------------------------
// Single fused kernel. grid = (L + ceil(T/ZFPB), B), 128 threads.
// Every block redundantly computes the per-batch duration scan (1KB of int32,
// L2-resident after the first block touches it; ~few hundred cycles, fully
// overlapped across all independent blocks -> no serialized prep kernel).
//
//  bx < L       : copy block for source position i=bx.
//                 Reads its 2KB row once, stores it to frames [start,start+d),
//                 writes d mask ones.
//  bx >= L      : tail block z=bx-L, chunk [z*ZFPB, z*ZFPB+ZFPB).
//                 Zero-fills frames >= total, writes mask zeros.
//                 Fully-active chunks exit right after the scan.
// ---------------------------------------------------------------------------
__global__ void __launch_bounds__(H4, 8)
k_fused(const float4* __restrict__ x4,
        const int*    __restrict__ dur,
        float4*       __restrict__ out4,
        float*        __restrict__ mask_out,
        int T) {
    const int b   = blockIdx.y;
    const int bx  = blockIdx.x;
    const int tid = threadIdx.x;          // 0..127
    const int lane = tid & 31;
    const int wid  = tid >> 5;            // 0..3

    __shared__ int s_warp[4];
    __shared__ int s_info[2];             // start, d for copy blocks

    // ---- redundant per-block scan of the 256 durations of batch b ----
    const int* drow = dur + b * L_DIM;
    const int d0 = __ldg(&drow[2 * tid]);
    const int d1 = __ldg(&drow[2 * tid + 1]);
    const int pair = d0 + d1;

    int v = pair;                          // warp inclusive scan of pair sums
    #pragma unroll
    for (int off = 1; off < 32; off <<= 1) {
        int n = __shfl_up_sync(0xffffffffu, v, off);
        if (lane >= off) v += n;
    }
    if (lane == 31) s_warp[wid] = v;
    __syncthreads();
    if (wid == 0 && lane < 4) {
        int w = s_warp[lane];
        #pragma unroll
        for (int off = 1; off < 4; off <<= 1) {
            int n = __shfl_up_sync(0x0000000Fu, w, off);
            if (lane >= off) w += n;
        }
        s_warp[lane] = w;
    }
    __syncthreads();

    const int incl  = v + ((wid > 0) ? s_warp[wid - 1] : 0);  // inclusive pair csum
    const int total = s_warp[3];                              // batch total

    if (bx < L_DIM) {
        // ---------------- copy block: source position i = bx ----------------
        if (tid == (bx >> 1)) {
            const int excl = incl - pair;                    // csum of pairs < this pair
            s_info[0] = excl + ((bx & 1) ? d0 : 0);          // start frame
            s_info[1] = (bx & 1) ? d1 : d0;                  // duration
        }
        __syncthreads();
        const int start = s_info[0];
        const int d     = s_info[1];
        if (d == 0) return;

        const int pos = b * L_DIM + bx;
        const float4 vrow = __ldg(&x4[(size_t)pos * H4 + tid]);

        float4* o = out4 + ((size_t)b * T + start) * H4 + tid;
        #pragma unroll 4
        for (int k = 0; k < d; ++k)
            o[(size_t)k * H4] = vrow;

        if (tid < d)
            mask_out[(size_t)b * T + start + tid] = 1.0f;
    } else {
        // ---------------- tail block: zero + mask for chunk ----------------
        const int t0 = (bx - L_DIM) * ZFPB;
        if (t0 + ZFPB <= total) return;    // fully active chunk

        const float4 z4 = make_float4(0.f, 0.f, 0.f, 0.f);
        #pragma unroll
        for (int k = 0; k < ZFPB; ++k) {
            const int t = t0 + k;
            if (t >= total && t < T)
                out4[((size_t)b * T + t) * H4 + tid] = z4;
        }
        if (tid < ZFPB) {
            const int t = t0 + tid;
            if (t >= total && t < T)
                mask_out[(size_t)b * T + t] = 0.0f;
        }
    }
}

// ---------------------------------------------------------------------------
extern "C" void kernel_launch(void* const* d_in, const int* in_sizes, int n_in,
                              void* d_out, int out_size) {
    const float* x   = (const float*)d_in[0];   // (B, L, H) float32
    const int*   dur = (const int*)d_in[1];     // (B, L)    int32

    // out_size = B*T*(H+1)  =>  T
    const int T = out_size / (B_DIM * (H_DIM + 1));

    float* out      = (float*)d_out;                          // (B, T, H)
    float* mask_out = out + (size_t)B_DIM * T * H_DIM;        // (B, T)

    const int ntail = (T + ZFPB - 1) / ZFPB;
    dim3 grid(L_DIM + ntail, B_DIM);
    k_fused<<<grid, H4>>>((const float4*)x, dur, (float4*)out, mask_out, T);

    (void)in_sizes; (void)n_in;
}

// round 7
// speedup vs baseline: 1.2875x; 1.2875x over previous
#include <cuda_runtime.h>
#include <cuda_bf16.h>
#include <cstdint>

// Problem constants (fixed by the dataset)
#define B_DIM 32
#define L_DIM 256
#define H_DIM 512
#define H4    (H_DIM / 4)      // 128 float4 per row
#define FPB   16               // frames per block

// ---------------------------------------------------------------------------
// Single fused frame-major kernel. grid = (ceil(T/FPB), B), 256 threads.
//  1. Redundant per-block scan of batch b's 256 durations (L2-resident).
//  2. Interval-overlap scatter: source index per frame into s_rows[FPB].
//  3. Dedup (rows non-decreasing) -> m unique rows, slot per frame.
//  4. Stage unique rows into SMEM (only L2 read traffic for x).
//  5. Frame-major stores: thread (c, fsub) writes 8 frames from SMEM,
//     plus the 16 mask floats. Tail frames (-1) write zeros / mask 0.
// ---------------------------------------------------------------------------
__global__ void __launch_bounds__(256, 6)
k_fused(const float4* __restrict__ x4,
        const int*    __restrict__ dur,
        float4*       __restrict__ out4,
        float*        __restrict__ mask_out,
        int T) {
    const int b    = blockIdx.y;
    const int t0   = blockIdx.x * FPB;
    const int tid  = threadIdx.x;         // 0..255
    const int lane = tid & 31;
    const int wid  = tid >> 5;            // 0..7

    __shared__ int    s_warp[8];
    __shared__ int    s_rows[FPB];        // source index per frame (-1 = tail)
    __shared__ int    s_slot[FPB];        // unique-row slot per frame (-1 = tail)
    __shared__ int    s_urow[FPB];        // unique source rows
    __shared__ int    s_m;                // number of unique rows
    __shared__ float4 s_stage[FPB * H4];  // staged unique rows (32KB)

    if (tid < FPB) s_rows[tid] = -1;

    // ---- scan of the 256 durations of batch b (1 per thread) ----
    const int d = __ldg(&dur[b * L_DIM + tid]);
    int v = d;
    #pragma unroll
    for (int off = 1; off < 32; off <<= 1) {
        int n = __shfl_up_sync(0xffffffffu, v, off);
        if (lane >= off) v += n;
    }
    if (lane == 31) s_warp[wid] = v;
    __syncthreads();
    if (wid == 0) {
        int w = (lane < 8) ? s_warp[lane] : 0;
        #pragma unroll
        for (int off = 1; off < 8; off <<= 1) {
            int n = __shfl_up_sync(0xffffffffu, w, off);
            if (lane >= off) w += n;
        }
        if (lane < 8) s_warp[lane] = w;
    }
    __syncthreads();

    const int incl  = v + ((wid > 0) ? s_warp[wid - 1] : 0);
    const int start = incl - d;

    // ---- scatter: mark frames in [t0, t0+FPB) covered by this thread ----
    {
        int lo = start > t0 ? start : t0;
        int hi = incl < t0 + FPB ? incl : t0 + FPB;
        for (int t = lo; t < hi; ++t)
            s_rows[t - t0] = tid;          // source position within batch
    }
    __syncthreads();

    // ---- dedup (rows non-decreasing; -1 only in a contiguous tail) ----
    if (tid < FPB) {
        const int r = s_rows[tid];
        const bool valid = (r >= 0);
        const bool flag  = valid && (tid == 0 || s_rows[tid - 1] != r);
        const unsigned bm = __ballot_sync(0x0000FFFFu, flag);
        if (flag) s_urow[__popc(bm & ((1u << tid) - 1))] = r;
        s_slot[tid] = valid ? (__popc(bm & ((2u << tid) - 1)) - 1) : -1;
        if (tid == 0) s_m = __popc(bm);
    }
    __syncthreads();

    // ---- stage the m unique rows into SMEM (2 rows per pass) ----
    const int m = s_m;
    const int c = tid & (H4 - 1);
    {
        const int jsub = tid >> 7;         // 0 or 1
        const size_t base = (size_t)b * L_DIM;
        for (int j = jsub; j < m; j += 2)
            s_stage[j * H4 + c] = __ldg(&x4[(base + s_urow[j]) * H4 + c]);
    }
    __syncthreads();

    // ---- frame-major stores: 8 frames per thread ----
    const int fsub = tid >> 7;             // 0 or 1
    const float4 z4 = make_float4(0.f, 0.f, 0.f, 0.f);
    #pragma unroll
    for (int k = 0; k < FPB / 2; ++k) {
        const int f = fsub + 2 * k;
        const int t = t0 + f;
        if (t < T) {
            const int slot = s_slot[f];
            const float4 vv = (slot >= 0) ? s_stage[slot * H4 + c] : z4;
            out4[((size_t)b * T + t) * H4 + c] = vv;
        }
    }

    // ---- mask ----
    if (tid < FPB) {
        const int t = t0 + tid;
        if (t < T)
            mask_out[(size_t)b * T + t] = (s_rows[tid] >= 0) ? 1.0f : 0.0f;
    }
}

// ---------------------------------------------------------------------------
extern "C" void kernel_launch(void* const* d_in, const int* in_sizes, int n_in,
                              void* d_out, int out_size) {
    const float* x   = (const float*)d_in[0];   // (B, L, H) float32
    const int*   dur = (const int*)d_in[1];     // (B, L)    int32

    // out_size = B*T*(H+1)  =>  T
    const int T = out_size / (B_DIM * (H_DIM + 1));

    float* out      = (float*)d_out;                          // (B, T, H)
    float* mask_out = out + (size_t)B_DIM * T * H_DIM;        // (B, T)

    dim3 grid((T + FPB - 1) / FPB, B_DIM);
    k_fused<<<grid, 256>>>((const float4*)x, dur, (float4*)out, mask_out, T);

    (void)in_sizes; (void)n_in;
}